// round 16
// baseline (speedup 1.0000x reference)
#include <cuda_runtime.h>
#include <math.h>

#define B_ 8
#define C_ 128
#define N_ 2048
#define H_ 4
#define K_ 32
#define D_ 32
#define F_ 512
#define P_ (B_*N_)
#define EPSbn 1e-5f

// ---------------- scratch (static device allocations only) ----------------
__device__ float g_S[B_*N_*N_];        // 128MB scores; later reused as hT [o][p] for FFN
__device__ int   g_idx[P_*K_];
__device__ float g_xq[P_*C_];
__device__ float g_xk[P_*C_];
__device__ float g_xv[P_*C_];
__device__ float g_x2[P_];
__device__ float g_s1[P_*C_];
__device__ float g_x1[P_*C_];          // [p][c]
__device__ float g_x1T[C_*P_];         // [c][p]
__device__ float g_s2[P_*C_];
__device__ float g_sum1[2*C_];
__device__ float g_sum2[2*C_];
__device__ float g_wqkvT[C_*384];      // [cin][3*cout]
__device__ float g_w1T[C_*F_];         // [cin][o]
__device__ float g_w2T[F_*C_];         // [o][cout]

// ---------------- packed fp32x2 helpers (sm_10x FFMA2 path) ----------------
#define FMA_F32X2(acc, a, b) \
    asm("fma.rn.f32x2 %0, %1, %2, %0;" : "+l"(acc) : "l"(a), "l"(b))
#define PACK2(dst, lo, hi) \
    asm("mov.b64 %0, {%1, %2};" : "=l"(dst) : "f"(lo), "f"(hi))
#define PACKDUP(dst, v) \
    asm("mov.b64 %0, {%1, %1};" : "=l"(dst) : "f"(v))
#define UNPACK2(lo, hi, src) \
    asm("mov.b64 {%0, %1}, %2;" : "=f"(lo), "=f"(hi) : "l"(src))

// ------- fused prep: zero BN sums + transpose weights + colnorm -------
__global__ void prep_kernel(const float* __restrict__ wq, const float* __restrict__ wk,
                            const float* __restrict__ wv, const float* __restrict__ w1,
                            const float* __restrict__ w2, const float* __restrict__ x) {
    int i = blockIdx.x*256 + threadIdx.x;
    if (i < 2*C_) { g_sum1[i] = 0.f; g_sum2[i] = 0.f; }
    if (i < 16384) {
        int r = i / C_, c = i % C_;
        g_wqkvT[c*384 + r] = wq[i];
    } else if (i < 32768) {
        int j = i - 16384; int r = j / C_, c = j % C_;
        g_wqkvT[c*384 + 128 + r] = wk[j];
    } else if (i < 49152) {
        int j = i - 32768; int r = j / C_, c = j % C_;
        g_wqkvT[c*384 + 256 + r] = wv[j];
    } else if (i < 114688) {
        int j = i - 49152; int r = j / C_, c = j % C_;     // w1: [F_][C_]
        g_w1T[(size_t)c*F_ + r] = w1[j];
    } else if (i < 180224) {
        int j = i - 114688; int r = j / F_, c = j % F_;    // w2: [C_][F_]
        g_w2T[(size_t)c*C_ + r] = w2[j];
    } else if (i < 180224 + P_) {
        int p = i - 180224;
        int b = p / N_, n = p % N_;
        const float* xb = x + (size_t)b*C_*N_ + n;
        float s = 0.f;
        #pragma unroll
        for (int c = 0; c < C_; c++) { float v = xb[(size_t)c*N_]; s += v*v; }
        g_x2[p] = s;
    }
}

// ---- double-buffered SGEMM mainloop: 128x128 tile, 8x8 micro, BK=16, FFMA2 --
__device__ __forceinline__ void sgemm_body(
    const float* __restrict__ Ag, long sA,
    const float* __restrict__ Bg, long sB,
    int KD, float acc[8][8],
    float (*As)[16][128], float (*Bs)[16][128], int t)
{
    int tx = t & 15, ty = t >> 4;
    int kk = t >> 5, mm = (t*4) & 127;
    unsigned long long acc2[8][4];
    #pragma unroll
    for (int iy = 0; iy < 8; iy++)
        #pragma unroll
        for (int ix = 0; ix < 4; ix++) acc2[iy][ix] = 0ull;

    *(float4*)&As[0][kk][mm]   = *(const float4*)&Ag[(long)kk*sA + mm];
    *(float4*)&As[0][kk+8][mm] = *(const float4*)&Ag[(long)(kk+8)*sA + mm];
    *(float4*)&Bs[0][kk][mm]   = *(const float4*)&Bg[(long)kk*sB + mm];
    *(float4*)&Bs[0][kk+8][mm] = *(const float4*)&Bg[(long)(kk+8)*sB + mm];
    __syncthreads();
    int nc = KD >> 4;
    for (int c = 0; c < nc; c++) {
        float4 an0, an1, bn0, bn1;
        bool more = (c + 1 < nc);
        if (more) {
            long ko = (long)((c + 1)*16 + kk);
            an0 = *(const float4*)&Ag[ko*sA + mm];
            an1 = *(const float4*)&Ag[(ko+8)*sA + mm];
            bn0 = *(const float4*)&Bg[ko*sB + mm];
            bn1 = *(const float4*)&Bg[(ko+8)*sB + mm];
        }
        int cur = c & 1;
        #pragma unroll
        for (int k = 0; k < 16; k++) {
            float4 av0 = *(float4*)&As[cur][k][ty*8];
            float4 av1 = *(float4*)&As[cur][k][ty*8+4];
            float4 bv0 = *(float4*)&Bs[cur][k][tx*8];
            float4 bv1 = *(float4*)&Bs[cur][k][tx*8+4];
            unsigned long long b2[4];
            PACK2(b2[0], bv0.x, bv0.y);
            PACK2(b2[1], bv0.z, bv0.w);
            PACK2(b2[2], bv1.x, bv1.y);
            PACK2(b2[3], bv1.z, bv1.w);
            float a[8] = {av0.x, av0.y, av0.z, av0.w, av1.x, av1.y, av1.z, av1.w};
            #pragma unroll
            for (int iy = 0; iy < 8; iy++) {
                unsigned long long a2;
                PACKDUP(a2, a[iy]);
                #pragma unroll
                for (int ix = 0; ix < 4; ix++)
                    FMA_F32X2(acc2[iy][ix], a2, b2[ix]);
            }
        }
        if (more) {
            int nxt = cur ^ 1;
            *(float4*)&As[nxt][kk][mm]   = an0;
            *(float4*)&As[nxt][kk+8][mm] = an1;
            *(float4*)&Bs[nxt][kk][mm]   = bn0;
            *(float4*)&Bs[nxt][kk+8][mm] = bn1;
            __syncthreads();
        }
    }
    #pragma unroll
    for (int iy = 0; iy < 8; iy++)
        #pragma unroll
        for (int ix = 0; ix < 4; ix++)
            UNPACK2(acc[iy][2*ix], acc[iy][2*ix+1], acc2[iy][ix]);
}

#define ACC_INIT float acc[8][8];                                   \
    _Pragma("unroll") for (int iy = 0; iy < 8; iy++)                \
    _Pragma("unroll") for (int ix = 0; ix < 8; ix++) acc[iy][ix] = 0.f;

// ---------------- score: S[n,m] = dot(x_n,x_m) - 0.5||x_m||^2, symmetric -----
// b = b0 + blockIdx.z (chunked launches for score/topk pipelining)
__global__ __launch_bounds__(256) void score_sgemm(const float* __restrict__ x, int b0) {
    const int T = 16;
    int L = blockIdx.x;
    int i = 0, rem = L;
    while (rem >= T - i) { rem -= (T - i); i++; }
    int j = i + rem;
    int n0 = i*128, m0 = j*128;
    int b = b0 + blockIdx.z;
    const float* xb  = x + (size_t)b*C_*N_;
    float* Sb        = g_S + (size_t)b*N_*N_;
    const float* x2b = g_x2 + b*N_;

    __shared__ float As[2][16][128], Bs[2][16][128];
    __shared__ float sbuf[16][132];
    int t = threadIdx.x, tx = t & 15, ty = t >> 4;
    ACC_INIT
    sgemm_body(xb + n0, N_, xb + m0, N_, C_, acc, As, Bs, t);

    int r0 = n0 + ty*8, c0 = m0 + tx*8;
    float x2r[8], x2c[8];
    #pragma unroll
    for (int q = 0; q < 8; q++) { x2r[q] = x2b[r0+q]; x2c[q] = 0.5f*x2b[c0+q]; }
    #pragma unroll
    for (int iy = 0; iy < 8; iy++) {
        float* row = &Sb[(size_t)(r0+iy)*N_ + c0];
        *(float4*)(row)   = make_float4(acc[iy][0]-x2c[0], acc[iy][1]-x2c[1],
                                        acc[iy][2]-x2c[2], acc[iy][3]-x2c[3]);
        *(float4*)(row+4) = make_float4(acc[iy][4]-x2c[4], acc[iy][5]-x2c[5],
                                        acc[iy][6]-x2c[6], acc[iy][7]-x2c[7]);
    }
    if (i != j) {
        int lr = t >> 4, lc = (t & 15)*8;
        #pragma unroll
        for (int ix = 0; ix < 8; ix++) {
            __syncthreads();
            #pragma unroll
            for (int iy = 0; iy < 8; iy++)
                sbuf[tx][ty*8 + iy] = acc[iy][ix] - 0.5f*x2r[iy];
            __syncthreads();
            float* dst = &Sb[(size_t)(m0 + lr*8 + ix)*N_ + n0 + lc];
            *(float4*)(dst)   = make_float4(sbuf[lr][lc],   sbuf[lr][lc+1],
                                            sbuf[lr][lc+2], sbuf[lr][lc+3]);
            *(float4*)(dst+4) = make_float4(sbuf[lr][lc+4], sbuf[lr][lc+5],
                                            sbuf[lr][lc+6], sbuf[lr][lc+7]);
        }
    }
}

// ---------------- fused q/k/v projection ----------------
__global__ __launch_bounds__(256) void proj_sgemm(const float* __restrict__ x) {
    int widx = blockIdx.x;
    int n0 = blockIdx.y*128;
    int b = blockIdx.z;
    const float* xb = x + (size_t)b*C_*N_;
    float* outp = (widx == 0 ? g_xq : widx == 1 ? g_xk : g_xv) + (size_t)b*N_*C_;

    __shared__ float As[2][16][128], Bs[2][16][128];
    int t = threadIdx.x, tx = t & 15, ty = t >> 4;
    ACC_INIT
    sgemm_body(xb + n0, N_, g_wqkvT + widx*128, 384, C_, acc, As, Bs, t);

    #pragma unroll
    for (int iy = 0; iy < 8; iy++) {
        int r = n0 + ty*8 + iy;
        float* row = &outp[(size_t)r*C_ + tx*8];
        *(float4*)(row)   = make_float4(acc[iy][0], acc[iy][1], acc[iy][2], acc[iy][3]);
        *(float4*)(row+4) = make_float4(acc[iy][4], acc[iy][5], acc[iy][6], acc[iy][7]);
    }
}

// ---------------- ffn1: hT[o][p] = leaky(sum_c x1T[c][p] * w1T[c][o]) ---------
__global__ __launch_bounds__(256) void ffn1_sgemm() {
    int o0 = blockIdx.x*128;
    int p0 = blockIdx.y*128;
    float* hT = g_S;

    __shared__ float As[2][16][128], Bs[2][16][128];
    int t = threadIdx.x, tx = t & 15, ty = t >> 4;
    ACC_INIT
    sgemm_body(g_x1T + p0, P_, g_w1T + o0, F_, C_, acc, As, Bs, t);

    #pragma unroll
    for (int ix = 0; ix < 8; ix++) {
        int col = o0 + tx*8 + ix;
        float v[8];
        #pragma unroll
        for (int iy = 0; iy < 8; iy++) {
            float u = acc[iy][ix];
            v[iy] = u > 0.f ? u : 0.2f*u;
        }
        float* cp = &hT[(size_t)col*P_ + p0 + ty*8];
        *(float4*)(cp)   = make_float4(v[0], v[1], v[2], v[3]);
        *(float4*)(cp+4) = make_float4(v[4], v[5], v[6], v[7]);
    }
}

// ---------------- ffn2: s2[p][c] = x1[p][c] + sum_o hT[o][p] * w2T[o][c] ------
__global__ __launch_bounds__(256) void ffn2_sgemm() {
    int p0 = blockIdx.y*128;
    const float* hT = g_S;

    __shared__ float As[2][16][128], Bs[2][16][128];
    int t = threadIdx.x, tx = t & 15, ty = t >> 4;
    ACC_INIT
    sgemm_body(hT + p0, P_, g_w2T, C_, F_, acc, As, Bs, t);

    #pragma unroll
    for (int iy = 0; iy < 8; iy++) {
        int r = p0 + ty*8 + iy;
        const float* resp = &g_x1[(size_t)r*C_ + tx*8];
        float* op = &g_s2[(size_t)r*C_ + tx*8];
        float4 e0 = *(const float4*)(resp);
        float4 e1 = *(const float4*)(resp+4);
        *(float4*)(op)   = make_float4(acc[iy][0]+e0.x, acc[iy][1]+e0.y,
                                       acc[iy][2]+e0.z, acc[iy][3]+e0.w);
        *(float4*)(op+4) = make_float4(acc[iy][4]+e1.x, acc[iy][5]+e1.y,
                                       acc[iy][6]+e1.z, acc[iy][7]+e1.w);
    }
}

// ---------------- top-32 per row: exact 4-pass radix select ----------------
__global__ __launch_bounds__(256) void topk_kernel(int base) {
    int row = base + blockIdx.x;
    const float4* S4 = (const float4*)(g_S + (size_t)row*N_);
    int t = threadIdx.x;
    unsigned u[8];
    {
        float4 v0 = S4[t*2], v1 = S4[t*2+1];
        float vv[8] = {v0.x, v0.y, v0.z, v0.w, v1.x, v1.y, v1.z, v1.w};
        #pragma unroll
        for (int q = 0; q < 8; q++) {
            unsigned b = __float_as_uint(vv[q]);
            u[q] = (b & 0x80000000u) ? ~b : (b | 0x80000000u);
        }
    }
    __shared__ unsigned hist[256];
    __shared__ unsigned suffix[256];
    __shared__ unsigned wsum[8];
    __shared__ unsigned sh_prefix;
    __shared__ int sh_need, sh_cnt, sh_eqcnt;
    __shared__ int eqbuf[256];
    if (t == 0) { sh_prefix = 0u; sh_need = K_; }
    int lane = t & 31, wid = t >> 5;

    #pragma unroll
    for (int pass = 0; pass < 4; pass++) {
        int shift = 24 - pass*8;
        hist[t] = 0u;
        __syncthreads();
        unsigned pref = sh_prefix;
        int need = sh_need;
        unsigned mask = (pass == 0) ? 0u : (0xFFFFFFFFu << (shift + 8));
        #pragma unroll
        for (int q = 0; q < 8; q++)
            if ((u[q] & mask) == pref)
                atomicAdd(&hist[(u[q] >> shift) & 255u], 1u);
        __syncthreads();
        int r = 255 - t;
        unsigned val = hist[r];
        #pragma unroll
        for (int o = 1; o < 32; o <<= 1) {
            unsigned up = __shfl_up_sync(0xffffffffu, val, o);
            if (lane >= o) val += up;
        }
        if (lane == 31) wsum[wid] = val;
        __syncthreads();
        #pragma unroll
        for (int w = 0; w < 8; w++) if (w < wid) val += wsum[w];
        suffix[r] = val;
        __syncthreads();
        unsigned nxt = (r == 255) ? 0u : suffix[r + 1];
        if (suffix[r] >= (unsigned)need && nxt < (unsigned)need) {
            sh_prefix = pref | ((unsigned)r << shift);
            sh_need = need - (int)nxt;
        }
        __syncthreads();
    }

    unsigned T = sh_prefix;
    int need_eq = sh_need;
    if (t == 0) { sh_cnt = 0; sh_eqcnt = 0; }
    __syncthreads();
    int* outp = g_idx + row*K_;
    #pragma unroll
    for (int q = 0; q < 8; q++) {
        if (u[q] > T) {
            int pos = atomicAdd(&sh_cnt, 1);
            outp[pos] = t*8 + q;
        } else if (u[q] == T) {
            int e = atomicAdd(&sh_eqcnt, 1);
            if (e < 256) eqbuf[e] = t*8 + q;
        }
    }
    __syncthreads();
    if (t == 0) {
        int cnt = sh_cnt;
        int m = sh_eqcnt; if (m > 256) m = 256;
        for (int i = 0; i < need_eq; i++) {
            int best = 0x7fffffff, bj = -1;
            for (int j = 0; j < m; j++)
                if (eqbuf[j] < best) { best = eqbuf[j]; bj = j; }
            eqbuf[bj] = 0x7fffffff;
            outp[cnt + i] = best;
        }
    }
}

// ---------------- attention: smem-staged neighbor K/V (coalesced gather) ------
__global__ __launch_bounds__(128) void attn_kernel(const float* __restrict__ x) {
    int p = blockIdx.x;
    int b = p >> 11, n = p & (N_-1);
    int t = threadIdx.x;
    int h = t >> 5, lane = t & 31;
    __shared__ float qs[C_], ks[C_], vs[C_];
    __shared__ float kn[K_][C_+1], vn[K_][C_+1];
    __shared__ float attns[H_][K_];
    __shared__ int idxs[K_];
    const float scale = 0.17677669529663687f;
    qs[t] = g_xq[(size_t)p*C_ + t] * scale;
    ks[t] = g_xk[(size_t)p*C_ + t];
    vs[t] = g_xv[(size_t)p*C_ + t];
    if (t < K_) idxs[t] = g_idx[p*K_ + t];
    __syncthreads();

    #pragma unroll
    for (int e = t; e < K_*C_; e += 128) {
        int j = e >> 7, c = e & (C_-1);
        size_t base = ((size_t)(b*N_ + idxs[j]))*C_ + c;
        kn[j][c] = g_xk[base];
        vn[j][c] = g_xv[base];
    }
    __syncthreads();

    float e = 0.f;
    #pragma unroll
    for (int d = 0; d < D_; d++)
        e += qs[h*D_ + d] * (kn[lane][h*D_ + d] - ks[h*D_ + d]);
    float mx = e;
    #pragma unroll
    for (int o = 16; o > 0; o >>= 1) mx = fmaxf(mx, __shfl_xor_sync(0xffffffffu, mx, o));
    float ex = __expf(e - mx);
    float sm = ex;
    #pragma unroll
    for (int o = 16; o > 0; o >>= 1) sm += __shfl_xor_sync(0xffffffffu, sm, o);
    attns[h][lane] = ex / sm;
    __syncwarp();

    float vself = vs[h*D_ + lane];
    float acc = 0.f;
    #pragma unroll
    for (int jj = 0; jj < K_; jj++)
        acc += attns[h][jj] * (vn[jj][h*D_ + lane] - vself);
    g_s1[(size_t)p*C_ + t] = x[(size_t)b*C_*N_ + (size_t)t*N_ + n] + acc;
}

// ---------------- BN stats ----------------
__global__ void bnstats_kernel(int which) {
    const float* src = which ? g_s2 : g_s1;
    float* sums      = which ? g_sum2 : g_sum1;
    int t = threadIdx.x;
    const float* base = src + (size_t)blockIdx.x*64*C_;
    float s = 0.f, ss = 0.f;
    #pragma unroll 8
    for (int q = 0; q < 64; q++) { float v = base[(size_t)q*C_ + t]; s += v; ss += v*v; }
    atomicAdd(&sums[t], s);
    atomicAdd(&sums[t + C_], ss);
}

// ---------------- x1 = BN1(s1) (stats inline) + tiled transpose -------------
__global__ void x1_kernel(const float* __restrict__ g1, const float* __restrict__ b1) {
    __shared__ float tile[32][33];
    int p0 = blockIdx.x*32;
    int c0 = blockIdx.y*32;
    int tx = threadIdx.x, ty = threadIdx.y;
    int c = c0 + tx;
    float m = g_sum1[c] * (1.f/(float)P_);
    float var = g_sum1[c + C_] * (1.f/(float)P_) - m*m;
    float inv = rsqrtf(var + EPSbn) * g1[c];
    float bb = b1[c];
    #pragma unroll
    for (int r = 0; r < 4; r++) {
        int pl = ty + r*8;
        float v = (g_s1[(size_t)(p0+pl)*C_ + c] - m) * inv + bb;
        g_x1[(size_t)(p0+pl)*C_ + c] = v;
        tile[pl][tx] = v;
    }
    __syncthreads();
    #pragma unroll
    for (int r = 0; r < 4; r++) {
        int cl = ty + r*8;
        g_x1T[(size_t)(c0+cl)*P_ + p0 + tx] = tile[tx][cl];
    }
}

// ---------------- final BN2 (stats inline) + transpose to [B,C,N] -----------
__global__ void out_kernel(float* __restrict__ out,
                           const float* __restrict__ g2, const float* __restrict__ b2) {
    __shared__ float tile[32][33];
    int b = blockIdx.z;
    int n0 = blockIdx.x*32, c0 = blockIdx.y*32;
    int tx = threadIdx.x, ty = threadIdx.y;
    int c = c0 + tx;
    float m = g_sum2[c] * (1.f/(float)P_);
    float var = g_sum2[c + C_] * (1.f/(float)P_) - m*m;
    float inv = rsqrtf(var + EPSbn) * g2[c];
    float bb = b2[c];
    #pragma unroll
    for (int r = 0; r < 4; r++) {
        int nl = ty + r*8;
        float v = (g_s2[(size_t)(b*N_ + n0 + nl)*C_ + c] - m) * inv + bb;
        tile[nl][tx] = v;
    }
    __syncthreads();
    #pragma unroll
    for (int r = 0; r < 4; r++) {
        int cl = ty + r*8;
        out[(size_t)b*C_*N_ + (size_t)(c0 + cl)*N_ + n0 + tx] = tile[tx][cl];
    }
}

// -------- launch: score/topk pipelined in 4 chunks; proj on 3rd stream -------
extern "C" void kernel_launch(void* const* d_in, const int* in_sizes, int n_in,
                              void* d_out, int out_size) {
    const float* x  = (const float*)d_in[0];
    const float* wq = (const float*)d_in[1];
    const float* wk = (const float*)d_in[2];
    const float* wv = (const float*)d_in[3];
    const float* w1 = (const float*)d_in[4];
    const float* w2 = (const float*)d_in[5];
    const float* g1 = (const float*)d_in[6];
    const float* b1 = (const float*)d_in[7];
    const float* g2 = (const float*)d_in[8];
    const float* b2 = (const float*)d_in[9];
    float* out = (float*)d_out;

    static cudaStream_t s1 = nullptr, s2 = nullptr;
    static cudaEvent_t evFork = nullptr, evProj = nullptr, evTop = nullptr;
    static cudaEvent_t evS[4] = {nullptr, nullptr, nullptr, nullptr};
    if (!s1) {
        cudaStreamCreateWithFlags(&s1, cudaStreamNonBlocking);
        cudaStreamCreateWithFlags(&s2, cudaStreamNonBlocking);
        cudaEventCreateWithFlags(&evFork, cudaEventDisableTiming);
        cudaEventCreateWithFlags(&evProj, cudaEventDisableTiming);
        cudaEventCreateWithFlags(&evTop, cudaEventDisableTiming);
        for (int c = 0; c < 4; c++)
            cudaEventCreateWithFlags(&evS[c], cudaEventDisableTiming);
    }

    prep_kernel<<<768, 256>>>(wq, wk, wv, w1, w2, x);
    cudaEventRecord(evFork, 0);

    // proj on s2, overlapping everything up to attn
    cudaStreamWaitEvent(s2, evFork, 0);
    proj_sgemm<<<dim3(3, N_/128, B_), 256, 0, s2>>>(x);
    cudaEventRecord(evProj, s2);

    // score in 4 chunks of 2 batches on main; topk chunk on s1 overlaps next score
    for (int c = 0; c < 4; c++) {
        score_sgemm<<<dim3(136, 1, 2), 256>>>(x, c*2);
        cudaEventRecord(evS[c], 0);
        cudaStreamWaitEvent(s1, evS[c], 0);
        topk_kernel<<<2*N_, 256, 0, s1>>>(c*2*N_);
    }
    cudaEventRecord(evTop, s1);

    cudaStreamWaitEvent(0, evTop, 0);
    cudaStreamWaitEvent(0, evProj, 0);
    attn_kernel<<<P_, 128>>>(x);

    bnstats_kernel<<<P_/64, 128>>>(0);
    x1_kernel<<<dim3(P_/32, C_/32), dim3(32, 8)>>>(g1, b1);

    ffn1_sgemm<<<dim3(F_/128, P_/128), 256>>>();
    ffn2_sgemm<<<dim3(1, P_/128), 256>>>();

    bnstats_kernel<<<P_/64, 128>>>(1);
    out_kernel<<<dim3(N_/32, C_/32, B_), dim3(32, 8)>>>(out, g2, b2);
}

// round 17
// speedup vs baseline: 1.6305x; 1.6305x over previous
#include <cuda_runtime.h>
#include <math.h>

#define B_ 8
#define C_ 128
#define N_ 2048
#define H_ 4
#define K_ 32
#define D_ 32
#define F_ 512
#define P_ (B_*N_)
#define EPSbn 1e-5f

// ---------------- scratch (static device allocations only) ----------------
__device__ float g_S[B_*N_*N_];        // 128MB scores; later reused as hT [o][p] for FFN
__device__ int   g_idx[P_*K_];
__device__ float g_xq[P_*C_];
__device__ float g_xk[P_*C_];
__device__ float g_xv[P_*C_];
__device__ float g_x2[P_];
__device__ float g_s1[P_*C_];
__device__ float g_x1[P_*C_];          // [p][c]
__device__ float g_x1T[C_*P_];         // [c][p]
__device__ float g_s2[P_*C_];
__device__ float g_sum1[2*C_];
__device__ float g_sum2[2*C_];
__device__ float g_wqkvT[C_*384];      // [cin][3*cout]
__device__ float g_w1T[C_*F_];         // [cin][o]
__device__ float g_w2T[F_*C_];         // [o][cout]

// ---------------- packed fp32x2 helpers (sm_10x FFMA2 path) ----------------
#define FMA_F32X2(acc, a, b) \
    asm("fma.rn.f32x2 %0, %1, %2, %0;" : "+l"(acc) : "l"(a), "l"(b))
#define PACK2(dst, lo, hi) \
    asm("mov.b64 %0, {%1, %2};" : "=l"(dst) : "f"(lo), "f"(hi))
#define PACKDUP(dst, v) \
    asm("mov.b64 %0, {%1, %1};" : "=l"(dst) : "f"(v))
#define UNPACK2(lo, hi, src) \
    asm("mov.b64 {%0, %1}, %2;" : "=f"(lo), "=f"(hi) : "l"(src))

// ------- fused prep: zero BN sums + transpose weights + colnorm -------
__global__ void prep_kernel(const float* __restrict__ wq, const float* __restrict__ wk,
                            const float* __restrict__ wv, const float* __restrict__ w1,
                            const float* __restrict__ w2, const float* __restrict__ x) {
    int i = blockIdx.x*256 + threadIdx.x;
    if (i < 2*C_) { g_sum1[i] = 0.f; g_sum2[i] = 0.f; }
    if (i < 16384) {
        int r = i / C_, c = i % C_;
        g_wqkvT[c*384 + r] = wq[i];
    } else if (i < 32768) {
        int j = i - 16384; int r = j / C_, c = j % C_;
        g_wqkvT[c*384 + 128 + r] = wk[j];
    } else if (i < 49152) {
        int j = i - 32768; int r = j / C_, c = j % C_;
        g_wqkvT[c*384 + 256 + r] = wv[j];
    } else if (i < 114688) {
        int j = i - 49152; int r = j / C_, c = j % C_;     // w1: [F_][C_]
        g_w1T[(size_t)c*F_ + r] = w1[j];
    } else if (i < 180224) {
        int j = i - 114688; int r = j / F_, c = j % F_;    // w2: [C_][F_]
        g_w2T[(size_t)c*C_ + r] = w2[j];
    } else if (i < 180224 + P_) {
        int p = i - 180224;
        int b = p / N_, n = p % N_;
        const float* xb = x + (size_t)b*C_*N_ + n;
        float s = 0.f;
        #pragma unroll
        for (int c = 0; c < C_; c++) { float v = xb[(size_t)c*N_]; s += v*v; }
        g_x2[p] = s;
    }
}

// ---- double-buffered SGEMM mainloop: 128x128 tile, 8x8 micro, BK=16, FFMA2 --
__device__ __forceinline__ void sgemm_body(
    const float* __restrict__ Ag, long sA,
    const float* __restrict__ Bg, long sB,
    int KD, float acc[8][8],
    float (*As)[16][128], float (*Bs)[16][128], int t)
{
    int tx = t & 15, ty = t >> 4;
    int kk = t >> 5, mm = (t*4) & 127;
    unsigned long long acc2[8][4];
    #pragma unroll
    for (int iy = 0; iy < 8; iy++)
        #pragma unroll
        for (int ix = 0; ix < 4; ix++) acc2[iy][ix] = 0ull;

    *(float4*)&As[0][kk][mm]   = *(const float4*)&Ag[(long)kk*sA + mm];
    *(float4*)&As[0][kk+8][mm] = *(const float4*)&Ag[(long)(kk+8)*sA + mm];
    *(float4*)&Bs[0][kk][mm]   = *(const float4*)&Bg[(long)kk*sB + mm];
    *(float4*)&Bs[0][kk+8][mm] = *(const float4*)&Bg[(long)(kk+8)*sB + mm];
    __syncthreads();
    int nc = KD >> 4;
    for (int c = 0; c < nc; c++) {
        float4 an0, an1, bn0, bn1;
        bool more = (c + 1 < nc);
        if (more) {
            long ko = (long)((c + 1)*16 + kk);
            an0 = *(const float4*)&Ag[ko*sA + mm];
            an1 = *(const float4*)&Ag[(ko+8)*sA + mm];
            bn0 = *(const float4*)&Bg[ko*sB + mm];
            bn1 = *(const float4*)&Bg[(ko+8)*sB + mm];
        }
        int cur = c & 1;
        #pragma unroll
        for (int k = 0; k < 16; k++) {
            float4 av0 = *(float4*)&As[cur][k][ty*8];
            float4 av1 = *(float4*)&As[cur][k][ty*8+4];
            float4 bv0 = *(float4*)&Bs[cur][k][tx*8];
            float4 bv1 = *(float4*)&Bs[cur][k][tx*8+4];
            unsigned long long b2[4];
            PACK2(b2[0], bv0.x, bv0.y);
            PACK2(b2[1], bv0.z, bv0.w);
            PACK2(b2[2], bv1.x, bv1.y);
            PACK2(b2[3], bv1.z, bv1.w);
            float a[8] = {av0.x, av0.y, av0.z, av0.w, av1.x, av1.y, av1.z, av1.w};
            #pragma unroll
            for (int iy = 0; iy < 8; iy++) {
                unsigned long long a2;
                PACKDUP(a2, a[iy]);
                #pragma unroll
                for (int ix = 0; ix < 4; ix++)
                    FMA_F32X2(acc2[iy][ix], a2, b2[ix]);
            }
        }
        if (more) {
            int nxt = cur ^ 1;
            *(float4*)&As[nxt][kk][mm]   = an0;
            *(float4*)&As[nxt][kk+8][mm] = an1;
            *(float4*)&Bs[nxt][kk][mm]   = bn0;
            *(float4*)&Bs[nxt][kk+8][mm] = bn1;
            __syncthreads();
        }
    }
    #pragma unroll
    for (int iy = 0; iy < 8; iy++)
        #pragma unroll
        for (int ix = 0; ix < 4; ix++)
            UNPACK2(acc[iy][2*ix], acc[iy][2*ix+1], acc2[iy][ix]);
}

#define ACC_INIT float acc[8][8];                                   \
    _Pragma("unroll") for (int iy = 0; iy < 8; iy++)                \
    _Pragma("unroll") for (int ix = 0; ix < 8; ix++) acc[iy][ix] = 0.f;

// ---------------- score: S[n,m] = dot(x_n,x_m) - 0.5||x_m||^2, symmetric -----
__global__ __launch_bounds__(256) void score_sgemm(const float* __restrict__ x) {
    const int T = 16;
    int L = blockIdx.x;
    int i = 0, rem = L;
    while (rem >= T - i) { rem -= (T - i); i++; }
    int j = i + rem;
    int n0 = i*128, m0 = j*128;
    int b = blockIdx.z;
    const float* xb  = x + (size_t)b*C_*N_;
    float* Sb        = g_S + (size_t)b*N_*N_;
    const float* x2b = g_x2 + b*N_;

    __shared__ float As[2][16][128], Bs[2][16][128];
    __shared__ float sbuf[16][132];
    int t = threadIdx.x, tx = t & 15, ty = t >> 4;
    ACC_INIT
    sgemm_body(xb + n0, N_, xb + m0, N_, C_, acc, As, Bs, t);

    int r0 = n0 + ty*8, c0 = m0 + tx*8;
    float x2r[8], x2c[8];
    #pragma unroll
    for (int q = 0; q < 8; q++) { x2r[q] = x2b[r0+q]; x2c[q] = 0.5f*x2b[c0+q]; }
    #pragma unroll
    for (int iy = 0; iy < 8; iy++) {
        float* row = &Sb[(size_t)(r0+iy)*N_ + c0];
        *(float4*)(row)   = make_float4(acc[iy][0]-x2c[0], acc[iy][1]-x2c[1],
                                        acc[iy][2]-x2c[2], acc[iy][3]-x2c[3]);
        *(float4*)(row+4) = make_float4(acc[iy][4]-x2c[4], acc[iy][5]-x2c[5],
                                        acc[iy][6]-x2c[6], acc[iy][7]-x2c[7]);
    }
    if (i != j) {
        int lr = t >> 4, lc = (t & 15)*8;
        #pragma unroll
        for (int ix = 0; ix < 8; ix++) {
            __syncthreads();
            #pragma unroll
            for (int iy = 0; iy < 8; iy++)
                sbuf[tx][ty*8 + iy] = acc[iy][ix] - 0.5f*x2r[iy];
            __syncthreads();
            float* dst = &Sb[(size_t)(m0 + lr*8 + ix)*N_ + n0 + lc];
            *(float4*)(dst)   = make_float4(sbuf[lr][lc],   sbuf[lr][lc+1],
                                            sbuf[lr][lc+2], sbuf[lr][lc+3]);
            *(float4*)(dst+4) = make_float4(sbuf[lr][lc+4], sbuf[lr][lc+5],
                                            sbuf[lr][lc+6], sbuf[lr][lc+7]);
        }
    }
}

// ---------------- fused q/k/v projection ----------------
__global__ __launch_bounds__(256) void proj_sgemm(const float* __restrict__ x) {
    int widx = blockIdx.x;
    int n0 = blockIdx.y*128;
    int b = blockIdx.z;
    const float* xb = x + (size_t)b*C_*N_;
    float* outp = (widx == 0 ? g_xq : widx == 1 ? g_xk : g_xv) + (size_t)b*N_*C_;

    __shared__ float As[2][16][128], Bs[2][16][128];
    int t = threadIdx.x, tx = t & 15, ty = t >> 4;
    ACC_INIT
    sgemm_body(xb + n0, N_, g_wqkvT + widx*128, 384, C_, acc, As, Bs, t);

    #pragma unroll
    for (int iy = 0; iy < 8; iy++) {
        int r = n0 + ty*8 + iy;
        float* row = &outp[(size_t)r*C_ + tx*8];
        *(float4*)(row)   = make_float4(acc[iy][0], acc[iy][1], acc[iy][2], acc[iy][3]);
        *(float4*)(row+4) = make_float4(acc[iy][4], acc[iy][5], acc[iy][6], acc[iy][7]);
    }
}

// ---------------- ffn1: hT[o][p] = leaky(sum_c x1T[c][p] * w1T[c][o]) ---------
__global__ __launch_bounds__(256) void ffn1_sgemm() {
    int o0 = blockIdx.x*128;
    int p0 = blockIdx.y*128;
    float* hT = g_S;

    __shared__ float As[2][16][128], Bs[2][16][128];
    int t = threadIdx.x, tx = t & 15, ty = t >> 4;
    ACC_INIT
    sgemm_body(g_x1T + p0, P_, g_w1T + o0, F_, C_, acc, As, Bs, t);

    #pragma unroll
    for (int ix = 0; ix < 8; ix++) {
        int col = o0 + tx*8 + ix;
        float v[8];
        #pragma unroll
        for (int iy = 0; iy < 8; iy++) {
            float u = acc[iy][ix];
            v[iy] = u > 0.f ? u : 0.2f*u;
        }
        float* cp = &hT[(size_t)col*P_ + p0 + ty*8];
        *(float4*)(cp)   = make_float4(v[0], v[1], v[2], v[3]);
        *(float4*)(cp+4) = make_float4(v[4], v[5], v[6], v[7]);
    }
}

// ---------------- ffn2: s2[p][c] = x1[p][c] + sum_o hT[o][p] * w2T[o][c] ------
__global__ __launch_bounds__(256) void ffn2_sgemm() {
    int p0 = blockIdx.y*128;
    const float* hT = g_S;

    __shared__ float As[2][16][128], Bs[2][16][128];
    int t = threadIdx.x, tx = t & 15, ty = t >> 4;
    ACC_INIT
    sgemm_body(hT + p0, P_, g_w2T, C_, F_, acc, As, Bs, t);

    #pragma unroll
    for (int iy = 0; iy < 8; iy++) {
        int r = p0 + ty*8 + iy;
        const float* resp = &g_x1[(size_t)r*C_ + tx*8];
        float* op = &g_s2[(size_t)r*C_ + tx*8];
        float4 e0 = *(const float4*)(resp);
        float4 e1 = *(const float4*)(resp+4);
        *(float4*)(op)   = make_float4(acc[iy][0]+e0.x, acc[iy][1]+e0.y,
                                       acc[iy][2]+e0.z, acc[iy][3]+e0.w);
        *(float4*)(op+4) = make_float4(acc[iy][4]+e1.x, acc[iy][5]+e1.y,
                                       acc[iy][6]+e1.z, acc[iy][7]+e1.w);
    }
}

// ---------------- top-32 per row: exact 4-pass radix select ----------------
__global__ __launch_bounds__(256) void topk_kernel() {
    int row = blockIdx.x;
    const float4* S4 = (const float4*)(g_S + (size_t)row*N_);
    int t = threadIdx.x;
    unsigned u[8];
    {
        float4 v0 = S4[t*2], v1 = S4[t*2+1];
        float vv[8] = {v0.x, v0.y, v0.z, v0.w, v1.x, v1.y, v1.z, v1.w};
        #pragma unroll
        for (int q = 0; q < 8; q++) {
            unsigned b = __float_as_uint(vv[q]);
            u[q] = (b & 0x80000000u) ? ~b : (b | 0x80000000u);
        }
    }
    __shared__ unsigned hist[256];
    __shared__ unsigned suffix[256];
    __shared__ unsigned wsum[8];
    __shared__ unsigned sh_prefix;
    __shared__ int sh_need, sh_cnt, sh_eqcnt;
    __shared__ int eqbuf[256];
    if (t == 0) { sh_prefix = 0u; sh_need = K_; }
    int lane = t & 31, wid = t >> 5;

    #pragma unroll
    for (int pass = 0; pass < 4; pass++) {
        int shift = 24 - pass*8;
        hist[t] = 0u;
        __syncthreads();
        unsigned pref = sh_prefix;
        int need = sh_need;
        unsigned mask = (pass == 0) ? 0u : (0xFFFFFFFFu << (shift + 8));
        #pragma unroll
        for (int q = 0; q < 8; q++)
            if ((u[q] & mask) == pref)
                atomicAdd(&hist[(u[q] >> shift) & 255u], 1u);
        __syncthreads();
        int r = 255 - t;
        unsigned val = hist[r];
        #pragma unroll
        for (int o = 1; o < 32; o <<= 1) {
            unsigned up = __shfl_up_sync(0xffffffffu, val, o);
            if (lane >= o) val += up;
        }
        if (lane == 31) wsum[wid] = val;
        __syncthreads();
        #pragma unroll
        for (int w = 0; w < 8; w++) if (w < wid) val += wsum[w];
        suffix[r] = val;
        __syncthreads();
        unsigned nxt = (r == 255) ? 0u : suffix[r + 1];
        if (suffix[r] >= (unsigned)need && nxt < (unsigned)need) {
            sh_prefix = pref | ((unsigned)r << shift);
            sh_need = need - (int)nxt;
        }
        __syncthreads();
    }

    unsigned T = sh_prefix;
    int need_eq = sh_need;
    if (t == 0) { sh_cnt = 0; sh_eqcnt = 0; }
    __syncthreads();
    int* outp = g_idx + row*K_;
    #pragma unroll
    for (int q = 0; q < 8; q++) {
        if (u[q] > T) {
            int pos = atomicAdd(&sh_cnt, 1);
            outp[pos] = t*8 + q;
        } else if (u[q] == T) {
            int e = atomicAdd(&sh_eqcnt, 1);
            if (e < 256) eqbuf[e] = t*8 + q;
        }
    }
    __syncthreads();
    if (t == 0) {
        int cnt = sh_cnt;
        int m = sh_eqcnt; if (m > 256) m = 256;
        for (int i = 0; i < need_eq; i++) {
            int best = 0x7fffffff, bj = -1;
            for (int j = 0; j < m; j++)
                if (eqbuf[j] < best) { best = eqbuf[j]; bj = j; }
            eqbuf[bj] = 0x7fffffff;
            outp[cnt + i] = best;
        }
    }
}

// ---------------- attention: smem-staged neighbor K/V (coalesced gather) ------
__global__ __launch_bounds__(128) void attn_kernel(const float* __restrict__ x) {
    int p = blockIdx.x;
    int b = p >> 11, n = p & (N_-1);
    int t = threadIdx.x;
    int h = t >> 5, lane = t & 31;
    __shared__ float qs[C_], ks[C_], vs[C_];
    __shared__ float kn[K_][C_+1], vn[K_][C_+1];
    __shared__ float attns[H_][K_];
    __shared__ int idxs[K_];
    const float scale = 0.17677669529663687f;
    qs[t] = g_xq[(size_t)p*C_ + t] * scale;
    ks[t] = g_xk[(size_t)p*C_ + t];
    vs[t] = g_xv[(size_t)p*C_ + t];
    if (t < K_) idxs[t] = g_idx[p*K_ + t];
    __syncthreads();

    #pragma unroll
    for (int e = t; e < K_*C_; e += 128) {
        int j = e >> 7, c = e & (C_-1);
        size_t base = ((size_t)(b*N_ + idxs[j]))*C_ + c;
        kn[j][c] = g_xk[base];
        vn[j][c] = g_xv[base];
    }
    __syncthreads();

    float e = 0.f;
    #pragma unroll
    for (int d = 0; d < D_; d++)
        e += qs[h*D_ + d] * (kn[lane][h*D_ + d] - ks[h*D_ + d]);
    float mx = e;
    #pragma unroll
    for (int o = 16; o > 0; o >>= 1) mx = fmaxf(mx, __shfl_xor_sync(0xffffffffu, mx, o));
    float ex = __expf(e - mx);
    float sm = ex;
    #pragma unroll
    for (int o = 16; o > 0; o >>= 1) sm += __shfl_xor_sync(0xffffffffu, sm, o);
    attns[h][lane] = ex / sm;
    __syncwarp();

    float vself = vs[h*D_ + lane];
    float acc = 0.f;
    #pragma unroll
    for (int jj = 0; jj < K_; jj++)
        acc += attns[h][jj] * (vn[jj][h*D_ + lane] - vself);
    g_s1[(size_t)p*C_ + t] = x[(size_t)b*C_*N_ + (size_t)t*N_ + n] + acc;
}

// ---------------- BN stats ----------------
__global__ void bnstats_kernel(int which) {
    const float* src = which ? g_s2 : g_s1;
    float* sums      = which ? g_sum2 : g_sum1;
    int t = threadIdx.x;
    const float* base = src + (size_t)blockIdx.x*64*C_;
    float s = 0.f, ss = 0.f;
    #pragma unroll 8
    for (int q = 0; q < 64; q++) { float v = base[(size_t)q*C_ + t]; s += v; ss += v*v; }
    atomicAdd(&sums[t], s);
    atomicAdd(&sums[t + C_], ss);
}

// ---------------- x1 = BN1(s1) (stats inline) + tiled transpose -------------
__global__ void x1_kernel(const float* __restrict__ g1, const float* __restrict__ b1) {
    __shared__ float tile[32][33];
    int p0 = blockIdx.x*32;
    int c0 = blockIdx.y*32;
    int tx = threadIdx.x, ty = threadIdx.y;
    int c = c0 + tx;
    float m = g_sum1[c] * (1.f/(float)P_);
    float var = g_sum1[c + C_] * (1.f/(float)P_) - m*m;
    float inv = rsqrtf(var + EPSbn) * g1[c];
    float bb = b1[c];
    #pragma unroll
    for (int r = 0; r < 4; r++) {
        int pl = ty + r*8;
        float v = (g_s1[(size_t)(p0+pl)*C_ + c] - m) * inv + bb;
        g_x1[(size_t)(p0+pl)*C_ + c] = v;
        tile[pl][tx] = v;
    }
    __syncthreads();
    #pragma unroll
    for (int r = 0; r < 4; r++) {
        int cl = ty + r*8;
        g_x1T[(size_t)(c0+cl)*P_ + p0 + tx] = tile[tx][cl];
    }
}

// ---------------- final BN2 (stats inline) + transpose to [B,C,N] -----------
__global__ void out_kernel(float* __restrict__ out,
                           const float* __restrict__ g2, const float* __restrict__ b2) {
    __shared__ float tile[32][33];
    int b = blockIdx.z;
    int n0 = blockIdx.x*32, c0 = blockIdx.y*32;
    int tx = threadIdx.x, ty = threadIdx.y;
    int c = c0 + tx;
    float m = g_sum2[c] * (1.f/(float)P_);
    float var = g_sum2[c + C_] * (1.f/(float)P_) - m*m;
    float inv = rsqrtf(var + EPSbn) * g2[c];
    float bb = b2[c];
    #pragma unroll
    for (int r = 0; r < 4; r++) {
        int nl = ty + r*8;
        float v = (g_s2[(size_t)(b*N_ + n0 + nl)*C_ + c] - m) * inv + bb;
        tile[nl][tx] = v;
    }
    __syncthreads();
    #pragma unroll
    for (int r = 0; r < 4; r++) {
        int cl = ty + r*8;
        out[(size_t)b*C_*N_ + (size_t)(c0 + cl)*N_ + n0 + tx] = tile[tx][cl];
    }
}

// ---------------- launch (two-stream fork/join: proj overlaps score+topk) ----
extern "C" void kernel_launch(void* const* d_in, const int* in_sizes, int n_in,
                              void* d_out, int out_size) {
    const float* x  = (const float*)d_in[0];
    const float* wq = (const float*)d_in[1];
    const float* wk = (const float*)d_in[2];
    const float* wv = (const float*)d_in[3];
    const float* w1 = (const float*)d_in[4];
    const float* w2 = (const float*)d_in[5];
    const float* g1 = (const float*)d_in[6];
    const float* b1 = (const float*)d_in[7];
    const float* g2 = (const float*)d_in[8];
    const float* b2 = (const float*)d_in[9];
    float* out = (float*)d_out;

    static cudaStream_t s1 = nullptr;
    static cudaEvent_t evFork = nullptr, evJoin = nullptr;
    if (!s1) {
        cudaStreamCreateWithFlags(&s1, cudaStreamNonBlocking);
        cudaEventCreateWithFlags(&evFork, cudaEventDisableTiming);
        cudaEventCreateWithFlags(&evJoin, cudaEventDisableTiming);
    }

    prep_kernel<<<768, 256>>>(wq, wk, wv, w1, w2, x);

    // fork: proj on side stream, score+topk on main stream
    cudaEventRecord(evFork, 0);
    cudaStreamWaitEvent(s1, evFork, 0);
    proj_sgemm<<<dim3(3, N_/128, B_), 256, 0, s1>>>(x);
    cudaEventRecord(evJoin, s1);

    score_sgemm<<<dim3(136, 1, B_), 256>>>(x);
    topk_kernel<<<P_, 256>>>();

    // join: attn needs topk (main) + proj (s1)
    cudaStreamWaitEvent(0, evJoin, 0);
    attn_kernel<<<P_, 128>>>(x);

    bnstats_kernel<<<P_/64, 128>>>(0);
    x1_kernel<<<dim3(P_/32, C_/32), dim3(32, 8)>>>(g1, b1);

    ffn1_sgemm<<<dim3(F_/128, P_/128), 256>>>();
    ffn2_sgemm<<<dim3(1, P_/128), 256>>>();

    bnstats_kernel<<<P_/64, 128>>>(1);
    out_kernel<<<dim3(N_/32, C_/32, B_), dim3(32, 8)>>>(out, g2, b2);
}